// round 13
// baseline (speedup 1.0000x reference)
#include <cuda_runtime.h>
#include <cuda_bf16.h>
#include <cstdint>
#include <cfloat>

#define N_Q     2048
#define M_ROWS  100000
#define DIMS    128
#define KNN     5

#define NSLICES   9
#define TILE_R    128
#define NTILES    87
#define SLICE_LEN (NTILES * TILE_R)   // 11136; 9*11136 >= 100000
#define QT        64                   // queries per CTA
#define TPB       256                  // 8 warps

#define KEEP      4                    // kept per (query, 16-col subset, slice)
#define TPQ_TOT   32                   // 8 subsets * KEEP
#define RSEL      24                   // exact-refined candidates per query

// Quantization scales: A stores round(-2F * SA), B stores round(B * SB).
#define SA 12.0f
#define SB 26.0f
#define INV_S (1.0f / (12.0f * 26.0f))

// ---- device scratch ----
__device__ uint32_t g_i8F2[N_Q * 32];     // s8(-2F*SA), 32 words/row (128 B)
__device__ uint32_t g_i8B [M_ROWS * 32];  // s8(B*SB)
__device__ float g_y2[M_ROWS];
__device__ float g_cand_val[NSLICES][N_Q][TPQ_TOT];
__device__ int   g_cand_idx[NSLICES][N_Q][TPQ_TOT];

// ---- smem layout (bytes) ----
#define AB_STRIDE 144                  // 128B row + 16B pad: conflict-free LDSM
#define SM_A    0                      // 64*144  = 9216
#define SM_B0   9216                   // 128*144 = 18432
#define SM_B1   27648
#define SM_Y2   46080                  // float[2][128]
#define SMEM_TOTAL 47104

// ---------------------------------------------------------------------------
__device__ __forceinline__ uint32_t s2u(const void* p) {
    uint32_t a;
    asm("{ .reg .u64 t; cvta.to.shared.u64 t, %1; cvt.u32.u64 %0, t; }" : "=r"(a) : "l"(p));
    return a;
}
__device__ __forceinline__ void cp16(uint32_t dst, const void* src) {
    asm volatile("cp.async.cg.shared.global [%0], [%1], 16;" :: "r"(dst), "l"(src) : "memory");
}
__device__ __forceinline__ void ldsm_x4(uint32_t& r0, uint32_t& r1, uint32_t& r2, uint32_t& r3,
                                        uint32_t addr) {
    asm volatile("ldmatrix.sync.aligned.m8n8.x4.shared.b16 {%0,%1,%2,%3}, [%4];"
                 : "=r"(r0), "=r"(r1), "=r"(r2), "=r"(r3) : "r"(addr));
}
// int8 IMMA: m16n8k32, s32 accumulate.
__device__ __forceinline__ void mma_s8(int& d0, int& d1, int& d2, int& d3,
                                       uint32_t a0, uint32_t a1, uint32_t a2, uint32_t a3,
                                       uint32_t b0, uint32_t b1) {
    asm volatile("mma.sync.aligned.m16n8k32.row.col.s32.s8.s8.s32 "
                 "{%0,%1,%2,%3}, {%4,%5,%6,%7}, {%8,%9}, {%0,%1,%2,%3};"
                 : "+r"(d0), "+r"(d1), "+r"(d2), "+r"(d3)
                 : "r"(a0), "r"(a1), "r"(a2), "r"(a3), "r"(b0), "r"(b1));
}
// Quantize 4 floats to 4 s8 bytes packed LE (byte0 = v0 .. byte3 = v3).
__device__ __forceinline__ uint32_t pack_s8x4(float v0, float v1, float v2, float v3) {
    int r0 = __float2int_rn(fminf(fmaxf(v0, -127.f), 127.f));
    int r1 = __float2int_rn(fminf(fmaxf(v1, -127.f), 127.f));
    int r2 = __float2int_rn(fminf(fmaxf(v2, -127.f), 127.f));
    int r3 = __float2int_rn(fminf(fmaxf(v3, -127.f), 127.f));
    return (uint32_t)(r0 & 0xFF) | ((uint32_t)(r1 & 0xFF) << 8) |
           ((uint32_t)(r2 & 0xFF) << 16) | ((uint32_t)r3 << 24);
}

// ---------------------------------------------------------------------------
// Convert: s8 quantized rows (+fold -2 and SA into features), y2 norms.
__global__ void convert_kernel(const float* __restrict__ F, const float* __restrict__ B) {
    int gw   = (blockIdx.x * blockDim.x + threadIdx.x) >> 5;
    int lane = threadIdx.x & 31;
    if (gw >= N_Q + M_ROWS) return;
    bool isF = gw < N_Q;
    int row  = isF ? gw : gw - N_Q;
    const float* src = (isF ? F : B) + (size_t)row * DIMS;
    float4 v = reinterpret_cast<const float4*>(src)[lane];
    if (!isF) {
        float s = v.x*v.x + v.y*v.y + v.z*v.z + v.w*v.w;
        #pragma unroll
        for (int o = 16; o; o >>= 1) s += __shfl_xor_sync(0xffffffffu, s, o);
        if (lane == 0) g_y2[row] = s;
    }
    float sc = isF ? (-2.0f * SA) : SB;
    uint32_t pk = pack_s8x4(sc * v.x, sc * v.y, sc * v.z, sc * v.w);
    (isF ? g_i8F2 : g_i8B)[(size_t)row * 32 + lane] = pk;
}

// ---------------------------------------------------------------------------
// Main: int8 IMMA GEMM + in-register top-4 selection. 2 CTAs/SM.
__global__ void __launch_bounds__(TPB, 2)
knn_mma_kernel() {
    extern __shared__ char smem[];
    const uint32_t sb = s2u(smem);
    float* y2s = reinterpret_cast<float*>(smem + SM_Y2);

    const int tid  = threadIdx.x;
    const int wid  = tid >> 5;
    const int lane = tid & 31;
    const int wm   = wid & 3;        // 4 m-chunks of 16 rows
    const int wn   = wid >> 2;       // 2 n-chunks of 64 cols
    const int qblock  = blockIdx.x * QT;
    const int slice   = blockIdx.y;
    const int row_beg = slice * SLICE_LEN;

    // Stage A (64 queries): 512 16B chunks (rows = 128B), 2 per thread.
    #pragma unroll
    for (int i = 0; i < 2; i++) {
        int chunk = tid + TPB * i;
        int r = chunk >> 3, cc = chunk & 7;
        uint4 v = *reinterpret_cast<const uint4*>(
            reinterpret_cast<const char*>(g_i8F2) + ((size_t)(qblock + r) * 128 + cc * 16));
        *reinterpret_cast<uint4*>(smem + SM_A + r * AB_STRIDE + cc * 16) = v;
    }
    // Prefetch B tile 0 into buffer 0 (1024 chunks, 4 per thread).
    {
        #pragma unroll
        for (int i = 0; i < 4; i++) {
            int chunk = tid + TPB * i;
            int r = chunk >> 3, cc = chunk & 7;
            int rg = row_beg + r;
            int rc = rg < M_ROWS ? rg : M_ROWS - 1;
            cp16(sb + SM_B0 + r * AB_STRIDE + cc * 16,
                 reinterpret_cast<const char*>(g_i8B) + ((size_t)rc * 128 + cc * 16));
        }
        if (tid < 128) {
            int rg = row_beg + tid;
            y2s[tid] = (rg < M_ROWS) ? g_y2[rg] : FLT_MAX;
        }
        asm volatile("cp.async.commit_group;" ::: "memory");
    }
    __syncthreads();

    // Hoist A fragments (16-row m-tile, K=128 s8 -> 16 regs), loop-invariant.
    const int arow = lane & 15;
    const int acol = (lane >> 4) * 16;
    const int brow = (lane & 7) + (lane >> 4) * 8;
    const int bcol = ((lane >> 3) & 1) * 16;
    const uint32_t Abase = sb + SM_A + (wm * 16) * AB_STRIDE;
    uint32_t afr[4][4];
    #pragma unroll
    for (int ks = 0; ks < 4; ks++)
        ldsm_x4(afr[ks][0], afr[ks][1], afr[ks][2], afr[ks][3],
                Abase + arow * AB_STRIDE + ks * 32 + acol);

    // Selection state: two owned query-rows, top-KEEP (ascending) each.
    float tv0[KEEP], tv1[KEEP]; int ti0[KEEP], ti1[KEEP];
    #pragma unroll
    for (int k = 0; k < KEEP; k++) {
        tv0[k] = FLT_MAX; ti0[k] = -1;
        tv1[k] = FLT_MAX; ti1[k] = -1;
    }

    for (int t = 0; t < NTILES; t++) {
        const int buf = t & 1;
        const uint32_t Bb = sb + (buf ? SM_B1 : SM_B0);

        __syncthreads();   // prev GEMM+select done; B[buf^1], y2s[buf^1] free

        if (t + 1 < NTILES) {
            int tb = row_beg + (t + 1) * TILE_R;
            uint32_t Bn = sb + (buf ? SM_B0 : SM_B1);
            #pragma unroll
            for (int i = 0; i < 4; i++) {
                int chunk = tid + TPB * i;
                int r = chunk >> 3, cc = chunk & 7;
                int rg = tb + r;
                int rc = rg < M_ROWS ? rg : M_ROWS - 1;
                cp16(Bn + r * AB_STRIDE + cc * 16,
                     reinterpret_cast<const char*>(g_i8B) + ((size_t)rc * 128 + cc * 16));
            }
            if (tid < 128) {
                int rg = tb + tid;
                y2s[(buf ^ 1) * 128 + tid] = (rg < M_ROWS) ? g_y2[rg] : FLT_MAX;
            }
            asm volatile("cp.async.commit_group;" ::: "memory");
            asm volatile("cp.async.wait_group 1;" ::: "memory");
        } else {
            asm volatile("cp.async.wait_group 0;" ::: "memory");
        }
        __syncthreads();   // B[buf] visible

        // ---- GEMM: warp tile 16(q) x 64(r), K=128 s8, A from registers
        int acc[8][4];
        #pragma unroll
        for (int nt = 0; nt < 8; nt++)
            #pragma unroll
            for (int e = 0; e < 4; e++) acc[nt][e] = 0;

        const uint32_t Bbase = Bb + (wn * 64) * AB_STRIDE;
        #pragma unroll
        for (int ks = 0; ks < 4; ks++) {
            uint32_t b[8][2];
            #pragma unroll
            for (int nt2 = 0; nt2 < 4; nt2++) {
                uint32_t r0, r1, r2, r3;
                ldsm_x4(r0, r1, r2, r3,
                        Bbase + (nt2 * 16 + brow) * AB_STRIDE + ks * 32 + bcol);
                b[nt2 * 2][0] = r0; b[nt2 * 2][1] = r1;
                b[nt2 * 2 + 1][0] = r2; b[nt2 * 2 + 1][1] = r3;
            }
            #pragma unroll
            for (int nt = 0; nt < 8; nt++)
                mma_s8(acc[nt][0], acc[nt][1], acc[nt][2], acc[nt][3],
                       afr[ks][0], afr[ks][1], afr[ks][2], afr[ks][3],
                       b[nt][0], b[nt][1]);
        }

        // ---- selection: d2 = y2[col] + acc*INV_S; min-gated top-KEEP
        const float* y2t = y2s + buf * 128;
        const int cbase = wn * 64 + 2 * (lane & 3);
        const int gidx  = row_beg + t * TILE_R + cbase;
        #pragma unroll
        for (int nt = 0; nt < 8; nt++) {
            int col = cbase + nt * 8;
            float2 y2p = *reinterpret_cast<const float2*>(y2t + col);
            float v00 = fmaf((float)acc[nt][0], INV_S, y2p.x);
            float v01 = fmaf((float)acc[nt][1], INV_S, y2p.y);
            float v10 = fmaf((float)acc[nt][2], INV_S, y2p.x);
            float v11 = fmaf((float)acc[nt][3], INV_S, y2p.y);
            int ib = gidx + nt * 8;

            if (fminf(v00, v01) < tv0[KEEP - 1]) {
                #pragma unroll
                for (int e = 0; e < 2; e++) {
                    float v = e ? v01 : v00;
                    if (v < tv0[KEEP - 1]) {
                        tv0[KEEP - 1] = v; ti0[KEEP - 1] = ib + e;
                        #pragma unroll
                        for (int k = KEEP - 1; k > 0; k--) {
                            if (tv0[k] < tv0[k - 1]) {
                                float tf = tv0[k - 1]; tv0[k - 1] = tv0[k]; tv0[k] = tf;
                                int   ti = ti0[k - 1]; ti0[k - 1] = ti0[k]; ti0[k] = ti;
                            }
                        }
                    }
                }
            }
            if (fminf(v10, v11) < tv1[KEEP - 1]) {
                #pragma unroll
                for (int e = 0; e < 2; e++) {
                    float v = e ? v11 : v10;
                    if (v < tv1[KEEP - 1]) {
                        tv1[KEEP - 1] = v; ti1[KEEP - 1] = ib + e;
                        #pragma unroll
                        for (int k = KEEP - 1; k > 0; k--) {
                            if (tv1[k] < tv1[k - 1]) {
                                float tf = tv1[k - 1]; tv1[k - 1] = tv1[k]; tv1[k] = tf;
                                int   ti = ti1[k - 1]; ti1[k - 1] = ti1[k]; ti1[k] = ti;
                            }
                        }
                    }
                }
            }
        }
    }

    // Write candidates: sub-list id = wn*4 + (lane&3), rows q0 and q0+8.
    const int q0  = qblock + wm * 16 + (lane >> 2);
    const int sub = wn * 4 + (lane & 3);
    #pragma unroll
    for (int k = 0; k < KEEP; k++) {
        g_cand_val[slice][q0][sub * KEEP + k]     = tv0[k];
        g_cand_idx[slice][q0][sub * KEEP + k]     = ti0[k];
        g_cand_val[slice][q0 + 8][sub * KEEP + k] = tv1[k];
        g_cand_idx[slice][q0 + 8][sub * KEEP + k] = ti1[k];
    }
}

// ---------------------------------------------------------------------------
// Refine: per query (one warp): approx-top-24 of 288 candidates -> exact fp32
// distances -> top-5 -> sqrt, normalize, mean.
__global__ void __launch_bounds__(256)
refine_kernel(const float* __restrict__ F, const float* __restrict__ B,
              const float* __restrict__ minv, const float* __restrict__ maxv,
              float* __restrict__ out) {
    __shared__ float sv[8][NSLICES * TPQ_TOT];
    __shared__ int   si[8][NSLICES * TPQ_TOT];
    __shared__ int   sel[8][RSEL];
    __shared__ float ex[8][RSEL];

    const int w    = threadIdx.x >> 5;
    const int lane = threadIdx.x & 31;
    const int q    = blockIdx.x * 8 + w;
    const int NC   = NSLICES * TPQ_TOT;   // 288

    for (int i = lane; i < NC; i += 32) {
        sv[w][i] = g_cand_val[i / TPQ_TOT][q][i % TPQ_TOT];
        si[w][i] = g_cand_idx[i / TPQ_TOT][q][i % TPQ_TOT];
    }
    __syncwarp();

    float4 xv = reinterpret_cast<const float4*>(F + (size_t)q * DIMS)[lane];
    float x2 = xv.x*xv.x + xv.y*xv.y + xv.z*xv.z + xv.w*xv.w;
    #pragma unroll
    for (int o = 16; o; o >>= 1) x2 += __shfl_xor_sync(0xffffffffu, x2, o);

    // Rank-select approx top-RSEL (strict order via (val, pos)).
    for (int i = lane; i < NC; i += 32) {
        float v = sv[w][i];
        int r = 0;
        for (int j = 0; j < NC; j++) {
            float u = sv[w][j];
            r += (u < v) || (u == v && j < i);
        }
        if (r < RSEL) sel[w][r] = si[w][i];
    }
    __syncwarp();

    for (int cc = 0; cc < RSEL; cc++) {
        int id = sel[w][cc];
        float d2 = FLT_MAX;
        if (id >= 0) {
            float4 yv = reinterpret_cast<const float4*>(B + (size_t)id * DIMS)[lane];
            float p = yv.x*yv.x + yv.y*yv.y + yv.z*yv.z + yv.w*yv.w
                    - 2.0f * (xv.x*yv.x + xv.y*yv.y + xv.z*yv.z + xv.w*yv.w);
            #pragma unroll
            for (int o = 16; o; o >>= 1) p += __shfl_xor_sync(0xffffffffu, p, o);
            d2 = x2 + p;
        }
        if (lane == 0) ex[w][cc] = d2;
    }
    __syncwarp();

    if (lane == 0) {
        float best[KNN];
        #pragma unroll
        for (int k = 0; k < KNN; k++) best[k] = FLT_MAX;
        #pragma unroll
        for (int cc = 0; cc < RSEL; cc++) {
            float v = ex[w][cc];
            if (v < best[KNN - 1]) {
                best[KNN - 1] = v;
                #pragma unroll
                for (int k = KNN - 1; k > 0; k--) {
                    if (best[k] < best[k - 1]) {
                        float tf = best[k - 1]; best[k - 1] = best[k]; best[k] = tf;
                    }
                }
            }
        }
        float mn = *minv, mx = *maxv;
        float inv = 1.f / (mx - mn);
        float sum = 0.f;
        #pragma unroll
        for (int k = 0; k < KNN; k++)
            sum += (sqrtf(fmaxf(best[k], 0.f)) - mn) * inv;
        out[q] = sum * (1.0f / KNN);
    }
}

// ---------------------------------------------------------------------------
extern "C" void kernel_launch(void* const* d_in, const int* in_sizes, int n_in,
                              void* d_out, int out_size) {
    const float* F    = (const float*)d_in[0];
    const float* B    = (const float*)d_in[1];
    const float* minv = (const float*)d_in[2];
    const float* maxv = (const float*)d_in[3];
    float* out = (float*)d_out;

    static bool attr_done = false;
    if (!attr_done) {
        cudaFuncSetAttribute(knn_mma_kernel,
                             cudaFuncAttributeMaxDynamicSharedMemorySize, SMEM_TOTAL);
        attr_done = true;
    }

    int conv_blocks = ((N_Q + M_ROWS) * 32 + 255) / 256;
    convert_kernel<<<conv_blocks, 256>>>(F, B);

    dim3 grid(N_Q / QT, NSLICES);
    knn_mma_kernel<<<grid, TPB, SMEM_TOTAL>>>();

    refine_kernel<<<N_Q / 8, 256>>>(F, B, minv, maxv, out);
}

// round 14
// speedup vs baseline: 1.5197x; 1.5197x over previous
#include <cuda_runtime.h>
#include <cuda_fp16.h>
#include <cstdint>
#include <cfloat>

#define N_Q     2048
#define M_ROWS  100000
#define DIMS    128
#define KNN     5

#define NSLICES   9
#define TILE_R    128
#define NTILES    87
#define SLICE_LEN (NTILES * TILE_R)   // 11136; 9*11136 >= 100000
#define QT        64                   // queries per CTA
#define TPB       256                  // 8 warps

#define KEEP      4                    // kept per (query, 16-col subset, slice)
#define TPQ_TOT   32                   // 8 subsets * KEEP
#define RSEL      24                   // exact-refined candidates per query

// ---- device scratch ----
__device__ __half g_hF2[N_Q * DIMS];     // f16(-2*F)
__device__ __half g_hB [M_ROWS * DIMS];  // f16(B)
__device__ float g_y2[M_ROWS];
__device__ float g_cand_val[NSLICES][N_Q][TPQ_TOT];
__device__ int   g_cand_idx[NSLICES][N_Q][TPQ_TOT];

// ---- smem layout (bytes) ----
#define AB_STRIDE 272                  // 256B f16 row + 16B pad: conflict-free LDSM
#define SM_A    0                      // 64*272  = 17408
#define SM_B0   17408                  // 128*272 = 34816
#define SM_B1   52224
#define SM_Y2   87040                  // float[2][128]
#define SMEM_TOTAL 88064

// ---------------------------------------------------------------------------
__device__ __forceinline__ uint32_t s2u(const void* p) {
    uint32_t a;
    asm("{ .reg .u64 t; cvta.to.shared.u64 t, %1; cvt.u32.u64 %0, t; }" : "=r"(a) : "l"(p));
    return a;
}
__device__ __forceinline__ void cp16(uint32_t dst, const void* src) {
    asm volatile("cp.async.cg.shared.global [%0], [%1], 16;" :: "r"(dst), "l"(src) : "memory");
}
__device__ __forceinline__ void ldsm_x4(uint32_t& r0, uint32_t& r1, uint32_t& r2, uint32_t& r3,
                                        uint32_t addr) {
    asm volatile("ldmatrix.sync.aligned.m8n8.x4.shared.b16 {%0,%1,%2,%3}, [%4];"
                 : "=r"(r0), "=r"(r1), "=r"(r2), "=r"(r3) : "r"(addr));
}
// f16-accumulate HMMA: m16n8k16, D/C are 2 x b32 (4 x f16).
// c0 = {(r,c),(r,c+1)}, c1 = {(r+8,c),(r+8,c+1)} — same positions as f32 acc.
__device__ __forceinline__ void mma_h(uint32_t& c0, uint32_t& c1,
                                      uint32_t a0, uint32_t a1, uint32_t a2, uint32_t a3,
                                      uint32_t b0, uint32_t b1) {
    asm volatile("mma.sync.aligned.m16n8k16.row.col.f16.f16.f16.f16 "
                 "{%0,%1}, {%2,%3,%4,%5}, {%6,%7}, {%0,%1};"
                 : "+r"(c0), "+r"(c1)
                 : "r"(a0), "r"(a1), "r"(a2), "r"(a3), "r"(b0), "r"(b1));
}

// ---------------------------------------------------------------------------
// Convert: f16(B) rows, f16(-2*F) rows, y2 norms. One warp per row.
__global__ void convert_kernel(const float* __restrict__ F, const float* __restrict__ B) {
    int gw   = (blockIdx.x * blockDim.x + threadIdx.x) >> 5;
    int lane = threadIdx.x & 31;
    if (gw >= N_Q + M_ROWS) return;
    bool isF = gw < N_Q;
    int row  = isF ? gw : gw - N_Q;
    const float* src = (isF ? F : B) + (size_t)row * DIMS;
    float4 v = reinterpret_cast<const float4*>(src)[lane];
    if (!isF) {
        float s = v.x*v.x + v.y*v.y + v.z*v.z + v.w*v.w;
        #pragma unroll
        for (int o = 16; o; o >>= 1) s += __shfl_xor_sync(0xffffffffu, s, o);
        if (lane == 0) g_y2[row] = s;
    }
    float sc = isF ? -2.0f : 1.0f;
    __half2 p0 = __floats2half2_rn(sc * v.x, sc * v.y);
    __half2 p1 = __floats2half2_rn(sc * v.z, sc * v.w);
    __half2* hp = reinterpret_cast<__half2*>(isF ? g_hF2 : g_hB);
    hp[(size_t)row * 64 + 2 * lane]     = p0;
    hp[(size_t)row * 64 + 2 * lane + 1] = p1;
}

// ---------------------------------------------------------------------------
// Main: f16-acc mma GEMM + in-register top-4 selection. 2 CTAs/SM.
__global__ void __launch_bounds__(TPB, 2)
knn_mma_kernel() {
    extern __shared__ char smem[];
    const uint32_t sb = s2u(smem);
    float* y2s = reinterpret_cast<float*>(smem + SM_Y2);

    const int tid  = threadIdx.x;
    const int wid  = tid >> 5;
    const int lane = tid & 31;
    const int wm   = wid & 3;        // 4 m-chunks of 16 rows
    const int wn   = wid >> 2;       // 2 n-chunks of 64 cols
    const int qblock  = blockIdx.x * QT;
    const int slice   = blockIdx.y;
    const int row_beg = slice * SLICE_LEN;

    // Stage A (64 queries): 1024 16B chunks (f16 rows = 256B), 4 per thread.
    #pragma unroll
    for (int i = 0; i < 4; i++) {
        int chunk = tid + TPB * i;
        int r = chunk >> 4, cc = chunk & 15;
        uint4 v = *reinterpret_cast<const uint4*>(
            reinterpret_cast<const char*>(g_hF2) + ((size_t)(qblock + r) * 256 + cc * 16));
        *reinterpret_cast<uint4*>(smem + SM_A + r * AB_STRIDE + cc * 16) = v;
    }
    // Prefetch B tile 0 into buffer 0 (2048 chunks, 8 per thread).
    {
        #pragma unroll
        for (int i = 0; i < 8; i++) {
            int chunk = tid + TPB * i;
            int r = chunk >> 4, cc = chunk & 15;
            int rg = row_beg + r;
            int rc = rg < M_ROWS ? rg : M_ROWS - 1;
            cp16(sb + SM_B0 + r * AB_STRIDE + cc * 16,
                 reinterpret_cast<const char*>(g_hB) + ((size_t)rc * 256 + cc * 16));
        }
        if (tid < 128) {
            int rg = row_beg + tid;
            y2s[tid] = (rg < M_ROWS) ? g_y2[rg] : FLT_MAX;
        }
        asm volatile("cp.async.commit_group;" ::: "memory");
    }
    __syncthreads();

    // Hoist A fragments (16-row m-tile, K=128 f16 -> 32 regs), loop-invariant.
    const int arow = lane & 15;
    const int acol = (lane >> 4) * 16;
    const int brow = (lane & 7) + (lane >> 4) * 8;
    const int bcol = ((lane >> 3) & 1) * 16;
    const uint32_t Abase = sb + SM_A + (wm * 16) * AB_STRIDE;
    uint32_t afr[8][4];
    #pragma unroll
    for (int ks = 0; ks < 8; ks++)
        ldsm_x4(afr[ks][0], afr[ks][1], afr[ks][2], afr[ks][3],
                Abase + arow * AB_STRIDE + ks * 32 + acol);

    // Selection state: two owned query-rows, top-KEEP (ascending) each.
    float tv0[KEEP], tv1[KEEP]; int ti0[KEEP], ti1[KEEP];
    #pragma unroll
    for (int k = 0; k < KEEP; k++) {
        tv0[k] = FLT_MAX; ti0[k] = -1;
        tv1[k] = FLT_MAX; ti1[k] = -1;
    }

    for (int t = 0; t < NTILES; t++) {
        const int buf = t & 1;
        const uint32_t Bb = sb + (buf ? SM_B1 : SM_B0);

        __syncthreads();   // prev GEMM+select done; B[buf^1], y2s[buf^1] free

        if (t + 1 < NTILES) {
            int tb = row_beg + (t + 1) * TILE_R;
            uint32_t Bn = sb + (buf ? SM_B0 : SM_B1);
            #pragma unroll
            for (int i = 0; i < 8; i++) {
                int chunk = tid + TPB * i;
                int r = chunk >> 4, cc = chunk & 15;
                int rg = tb + r;
                int rc = rg < M_ROWS ? rg : M_ROWS - 1;
                cp16(Bn + r * AB_STRIDE + cc * 16,
                     reinterpret_cast<const char*>(g_hB) + ((size_t)rc * 256 + cc * 16));
            }
            if (tid < 128) {
                int rg = tb + tid;
                y2s[(buf ^ 1) * 128 + tid] = (rg < M_ROWS) ? g_y2[rg] : FLT_MAX;
            }
            asm volatile("cp.async.commit_group;" ::: "memory");
            asm volatile("cp.async.wait_group 1;" ::: "memory");
        } else {
            asm volatile("cp.async.wait_group 0;" ::: "memory");
        }
        __syncthreads();   // B[buf] visible

        // ---- GEMM: warp tile 16(q) x 64(r), K=128, f16 accumulate
        uint32_t acc[8][2];
        #pragma unroll
        for (int nt = 0; nt < 8; nt++) { acc[nt][0] = 0u; acc[nt][1] = 0u; }

        const uint32_t Bbase = Bb + (wn * 64) * AB_STRIDE;
        #pragma unroll
        for (int ks = 0; ks < 8; ks++) {
            uint32_t b[8][2];
            #pragma unroll
            for (int nt2 = 0; nt2 < 4; nt2++) {
                uint32_t r0, r1, r2, r3;
                ldsm_x4(r0, r1, r2, r3,
                        Bbase + (nt2 * 16 + brow) * AB_STRIDE + ks * 32 + bcol);
                b[nt2 * 2][0] = r0; b[nt2 * 2][1] = r1;
                b[nt2 * 2 + 1][0] = r2; b[nt2 * 2 + 1][1] = r3;
            }
            #pragma unroll
            for (int nt = 0; nt < 8; nt++)
                mma_h(acc[nt][0], acc[nt][1],
                      afr[ks][0], afr[ks][1], afr[ks][2], afr[ks][3],
                      b[nt][0], b[nt][1]);
        }

        // ---- selection: unpack f16x2, d2 = val + y2[col]; min-gated top-KEEP
        const float* y2t = y2s + buf * 128;
        const int cbase = wn * 64 + 2 * (lane & 3);
        const int gidx  = row_beg + t * TILE_R + cbase;
        #pragma unroll
        for (int nt = 0; nt < 8; nt++) {
            int col = cbase + nt * 8;
            float2 y2p = *reinterpret_cast<const float2*>(y2t + col);
            float2 f0 = __half22float2(*reinterpret_cast<const __half2*>(&acc[nt][0]));
            float2 f1 = __half22float2(*reinterpret_cast<const __half2*>(&acc[nt][1]));
            float v00 = f0.x + y2p.x, v01 = f0.y + y2p.y;
            float v10 = f1.x + y2p.x, v11 = f1.y + y2p.y;
            int ib = gidx + nt * 8;

            if (fminf(v00, v01) < tv0[KEEP - 1]) {
                #pragma unroll
                for (int e = 0; e < 2; e++) {
                    float v = e ? v01 : v00;
                    if (v < tv0[KEEP - 1]) {
                        tv0[KEEP - 1] = v; ti0[KEEP - 1] = ib + e;
                        #pragma unroll
                        for (int k = KEEP - 1; k > 0; k--) {
                            if (tv0[k] < tv0[k - 1]) {
                                float tf = tv0[k - 1]; tv0[k - 1] = tv0[k]; tv0[k] = tf;
                                int   ti = ti0[k - 1]; ti0[k - 1] = ti0[k]; ti0[k] = ti;
                            }
                        }
                    }
                }
            }
            if (fminf(v10, v11) < tv1[KEEP - 1]) {
                #pragma unroll
                for (int e = 0; e < 2; e++) {
                    float v = e ? v11 : v10;
                    if (v < tv1[KEEP - 1]) {
                        tv1[KEEP - 1] = v; ti1[KEEP - 1] = ib + e;
                        #pragma unroll
                        for (int k = KEEP - 1; k > 0; k--) {
                            if (tv1[k] < tv1[k - 1]) {
                                float tf = tv1[k - 1]; tv1[k - 1] = tv1[k]; tv1[k] = tf;
                                int   ti = ti1[k - 1]; ti1[k - 1] = ti1[k]; ti1[k] = ti;
                            }
                        }
                    }
                }
            }
        }
    }

    // Write candidates: sub-list id = wn*4 + (lane&3), rows q0 and q0+8.
    const int q0  = qblock + wm * 16 + (lane >> 2);
    const int sub = wn * 4 + (lane & 3);
    #pragma unroll
    for (int k = 0; k < KEEP; k++) {
        g_cand_val[slice][q0][sub * KEEP + k]     = tv0[k];
        g_cand_idx[slice][q0][sub * KEEP + k]     = ti0[k];
        g_cand_val[slice][q0 + 8][sub * KEEP + k] = tv1[k];
        g_cand_idx[slice][q0 + 8][sub * KEEP + k] = ti1[k];
    }
}

// ---------------------------------------------------------------------------
// Refine: per query (one warp): approx-top-24 of 288 candidates -> exact fp32
// distances -> top-5 -> sqrt, normalize, mean.
__global__ void __launch_bounds__(256)
refine_kernel(const float* __restrict__ F, const float* __restrict__ B,
              const float* __restrict__ minv, const float* __restrict__ maxv,
              float* __restrict__ out) {
    __shared__ float sv[8][NSLICES * TPQ_TOT];
    __shared__ int   si[8][NSLICES * TPQ_TOT];
    __shared__ int   sel[8][RSEL];
    __shared__ float ex[8][RSEL];

    const int w    = threadIdx.x >> 5;
    const int lane = threadIdx.x & 31;
    const int q    = blockIdx.x * 8 + w;
    const int NC   = NSLICES * TPQ_TOT;   // 288

    for (int i = lane; i < NC; i += 32) {
        sv[w][i] = g_cand_val[i / TPQ_TOT][q][i % TPQ_TOT];
        si[w][i] = g_cand_idx[i / TPQ_TOT][q][i % TPQ_TOT];
    }
    __syncwarp();

    float4 xv = reinterpret_cast<const float4*>(F + (size_t)q * DIMS)[lane];
    float x2 = xv.x*xv.x + xv.y*xv.y + xv.z*xv.z + xv.w*xv.w;
    #pragma unroll
    for (int o = 16; o; o >>= 1) x2 += __shfl_xor_sync(0xffffffffu, x2, o);

    // Rank-select approx top-RSEL (strict order via (val, pos)).
    for (int i = lane; i < NC; i += 32) {
        float v = sv[w][i];
        int r = 0;
        for (int j = 0; j < NC; j++) {
            float u = sv[w][j];
            r += (u < v) || (u == v && j < i);
        }
        if (r < RSEL) sel[w][r] = si[w][i];
    }
    __syncwarp();

    for (int cc = 0; cc < RSEL; cc++) {
        int id = sel[w][cc];
        float d2 = FLT_MAX;
        if (id >= 0) {
            float4 yv = reinterpret_cast<const float4*>(B + (size_t)id * DIMS)[lane];
            float p = yv.x*yv.x + yv.y*yv.y + yv.z*yv.z + yv.w*yv.w
                    - 2.0f * (xv.x*yv.x + xv.y*yv.y + xv.z*yv.z + xv.w*yv.w);
            #pragma unroll
            for (int o = 16; o; o >>= 1) p += __shfl_xor_sync(0xffffffffu, p, o);
            d2 = x2 + p;
        }
        if (lane == 0) ex[w][cc] = d2;
    }
    __syncwarp();

    if (lane == 0) {
        float best[KNN];
        #pragma unroll
        for (int k = 0; k < KNN; k++) best[k] = FLT_MAX;
        #pragma unroll
        for (int cc = 0; cc < RSEL; cc++) {
            float v = ex[w][cc];
            if (v < best[KNN - 1]) {
                best[KNN - 1] = v;
                #pragma unroll
                for (int k = KNN - 1; k > 0; k--) {
                    if (best[k] < best[k - 1]) {
                        float tf = best[k - 1]; best[k - 1] = best[k]; best[k] = tf;
                    }
                }
            }
        }
        float mn = *minv, mx = *maxv;
        float inv = 1.f / (mx - mn);
        float sum = 0.f;
        #pragma unroll
        for (int k = 0; k < KNN; k++)
            sum += (sqrtf(fmaxf(best[k], 0.f)) - mn) * inv;
        out[q] = sum * (1.0f / KNN);
    }
}

// ---------------------------------------------------------------------------
extern "C" void kernel_launch(void* const* d_in, const int* in_sizes, int n_in,
                              void* d_out, int out_size) {
    const float* F    = (const float*)d_in[0];
    const float* B    = (const float*)d_in[1];
    const float* minv = (const float*)d_in[2];
    const float* maxv = (const float*)d_in[3];
    float* out = (float*)d_out;

    static bool attr_done = false;
    if (!attr_done) {
        cudaFuncSetAttribute(knn_mma_kernel,
                             cudaFuncAttributeMaxDynamicSharedMemorySize, SMEM_TOTAL);
        attr_done = true;
    }

    int conv_blocks = ((N_Q + M_ROWS) * 32 + 255) / 256;
    convert_kernel<<<conv_blocks, 256>>>(F, B);

    dim3 grid(N_Q / QT, NSLICES);
    knn_mma_kernel<<<grid, TPB, SMEM_TOTAL>>>();

    refine_kernel<<<N_Q / 8, 256>>>(F, B, minv, maxv, out);
}